// round 11
// baseline (speedup 1.0000x reference)
#include <cuda_runtime.h>
#include <math.h>

// Problem constants (fixed by the reference generator)
#define BB    256      // batch
#define B4    (BB/4)
#define NN    768      // codeword length
#define HH    3072     // edges
#define NL    19       // hidden VN layers
#define CAP   16       // storage stride per sparse row (16 ints/floats, 64B)
#define CLIPV 0.999999f
#define NBLK  384      // persistent chain blocks (<= 4*152 co-resident, no deadlock)

// ---------------------------------------------------------------------------
// Scratch: __device__ globals (no allocation allowed anywhere)
// ---------------------------------------------------------------------------
__device__ int   g_vn_sidx[HH * CAP];          // shared W_vn row structure
__device__ int   g_vn_scnt[HH];
__device__ float g_wvn_val[NL * HH * CAP];     // per-layer values

__device__ int   g_s_sidx[NN * CAP];           // shared S column structure
__device__ int   g_s_scnt[NN];
__device__ float g_s_val[20 * NN * CAP];

__device__ int   g_tmp_idx[2 * HH * CAP];
__device__ float g_tmp_val[2 * HH * CAP];
__device__ int   g_tmp_cnt[2 * HH];

__device__ int   g_mcn_idx[HH * CAP];
__device__ int   g_mcn_cnt[HH];

__device__ int   g_mf_idx[HH * CAP];
__device__ int   g_mf_cnt[HH];

__device__ int   g_wout_idx[NN * CAP];
__device__ float g_wout_val[NN * CAP];
__device__ int   g_wout_cnt[NN];

__device__ int   g_bm_idx[HH * CAP];
__device__ float g_bm_val[HH * CAP];
__device__ int   g_bm_cnt[HH];

__device__ int   g_cm_idx[NN * CAP];
__device__ float g_cm_val[NN * CAP];
__device__ int   g_cm_cnt[NN];

__device__ float g_xT[(NN + 1) * BB];   // x transposed [n][b]; row NN = sentinel 40.0
__device__ float g_C[20 * NN * BB];     // C_l = llr @ S[l], layout [l][r][b]
__device__ float g_h[(HH + 1) * BB];    // tanh state [i][b]; row HH = sentinel 1.0
__device__ float g_g[HH * BB];          // 2*atanh(clip(state)), layout [i][b]

// software grid barrier state (persists across replays; epoch is relative)
__device__ unsigned g_bar_arrive = 0;
__device__ unsigned g_bar_epoch  = 0;

// ---------------------------------------------------------------------------
// Row extractor (proven). Pads idx with `padidx`, val with 0, up to CAP.
// Deterministic: output order == column order.
// ---------------------------------------------------------------------------
template<int COLS>
__global__ void extract_rows_fast(const float* __restrict__ M, int rows,
                                  int* __restrict__ idx, float* __restrict__ val,
                                  int* __restrict__ cnt, int padidx) {
    int gw   = (blockIdx.x * blockDim.x + threadIdx.x) >> 5;
    int lane = threadIdx.x & 31;
    if (gw >= rows) return;
    const float4* p = reinterpret_cast<const float4*>(M) + (size_t)gw * (COLS >> 2);
    constexpr int NIT = COLS >> 7;
    unsigned hit = 0;
#pragma unroll
    for (int it = 0; it < NIT; ++it) {
        float4 v = p[it * 32 + lane];
        bool h = (v.x != 0.f) | (v.y != 0.f) | (v.z != 0.f) | (v.w != 0.f);
        hit |= (h ? 1u : 0u) << it;
    }
    unsigned ah = __reduce_or_sync(0xffffffffu, hit);
    int c = 0;
    while (ah) {
        int it = __ffs(ah) - 1;
        ah &= ah - 1;
        float4 v = p[it * 32 + lane];
        float e[4] = {v.x, v.y, v.z, v.w};
#pragma unroll
        for (int k = 0; k < 4; ++k) {
            unsigned m = __ballot_sync(0xffffffffu, e[k] != 0.0f);
            if (e[k] != 0.0f) {
                int pos = c + __popc(m & ((1u << lane) - 1u));
                if (pos < CAP) {
                    idx[(size_t)gw * CAP + pos] = it * 128 + lane * 4 + k;
                    if (val) val[(size_t)gw * CAP + pos] = e[k];
                }
            }
            c += __popc(m);
        }
    }
    if (lane >= c && lane < CAP) {
        idx[(size_t)gw * CAP + lane] = padidx;
        if (val) val[(size_t)gw * CAP + lane] = 0.0f;
    }
    if (lane == 0) cnt[gw] = (c < CAP) ? c : CAP;
}

// One thread per column; coalesced across threads. blockIdx.y = layer.
__global__ void extract_cols_k(const float* __restrict__ M, int rows, int cols,
                               size_t mstride,
                               int* __restrict__ idx, float* __restrict__ val,
                               int* __restrict__ cnt) {
    int l = blockIdx.y;
    int c = blockIdx.x * blockDim.x + threadIdx.x;
    if (c >= cols) return;
    const float* Mb   = M   + (size_t)l * mstride;
    int*         idxb = idx + (size_t)l * cols * CAP;
    float*       valb = val + (size_t)l * cols * CAP;
    int n = 0;
#pragma unroll 16
    for (int r = 0; r < rows; ++r) {
        float v = Mb[(size_t)r * cols + c];
        if (v != 0.0f) {
            if (n < CAP) { idxb[c * CAP + n] = r; valb[c * CAP + n] = v; }
            n++;
        }
    }
    int nn = (n < CAP) ? n : CAP;
    for (int t = nn; t < CAP; ++t) { idxb[c * CAP + t] = 0; valb[c * CAP + t] = 0.0f; }
    cnt[c + l * cols] = nn;
}

// Union of two per-row sorted index lists -> shared structure (zero-padded).
__global__ void union_rows_k(const int* __restrict__ t_idx,
                             const int* __restrict__ t_cnt, int rows,
                             int* __restrict__ sidx, int* __restrict__ scnt) {
    int i = blockIdx.x * blockDim.x + threadIdx.x;
    if (i >= rows) return;
    const int* a = t_idx + (size_t)i * CAP;          int na = t_cnt[i];
    const int* b = t_idx + (size_t)(rows + i) * CAP; int nb = t_cnt[rows + i];
    int pa = 0, pb = 0, n = 0;
    while ((pa < na || pb < nb) && n < CAP) {
        int va = (pa < na) ? a[pa] : 0x7fffffff;
        int vb = (pb < nb) ? b[pb] : 0x7fffffff;
        int v = (va < vb) ? va : vb;
        if (va == v) pa++;
        if (vb == v) pb++;
        sidx[i * CAP + n++] = v;
    }
    scnt[i] = n;
    for (; n < CAP; ++n) sidx[i * CAP + n] = 0;
}

// Gather per-layer values at the shared structure positions (zero-pads).
__global__ void gather_vals_k(const float* __restrict__ M, size_t lstride,
                              size_t rstride, size_t estride,
                              int rows, int layers,
                              const int* __restrict__ sidx,
                              const int* __restrict__ scnt,
                              float* __restrict__ val) {
    int gid = blockIdx.x * blockDim.x + threadIdx.x;
    int t  = gid & (CAP - 1);
    int ri = gid >> 4;
    if (ri >= layers * rows) return;
    int l = ri / rows, i = ri - l * rows;
    float v = 0.0f;
    if (t < scnt[i])
        v = M[(size_t)l * lstride + (size_t)i * rstride +
              (size_t)sidx[i * CAP + t] * estride];
    val[(size_t)ri * CAP + t] = v;
}

// ---------------------------------------------------------------------------
// Fast-math helpers (tolerance 1e-3; these land ~1e-6)
// ---------------------------------------------------------------------------
__device__ __forceinline__ float fast_tanh_half(float z) {  // tanh(0.5*z)
    z = fminf(fmaxf(z, -30.0f), 30.0f);
    float e = __expf(z);
    return __fdividef(e - 1.0f, e + 1.0f);
}
__device__ __forceinline__ float clip_atanh2(float p) {     // 2*atanh(clip(p))
    p = fminf(fmaxf(p, -CLIPV), CLIPV);
    return __logf(__fdividef(1.0f + p, 1.0f - p));
}

// ---------------------------------------------------------------------------
// Pre-chain kernels
// ---------------------------------------------------------------------------
__global__ void transpose_x_k(const float* __restrict__ x) {
    __shared__ float tile[32][33];
    int n0 = blockIdx.x * 32, b0 = blockIdx.y * 32;
    int tx = threadIdx.x, ty = threadIdx.y;
#pragma unroll
    for (int k = 0; k < 32; k += 8)
        tile[ty + k][tx] = x[(size_t)(b0 + ty + k) * NN + n0 + tx];
    __syncthreads();
#pragma unroll
    for (int k = 0; k < 32; k += 8)
        g_xT[(size_t)(n0 + ty + k) * BB + b0 + tx] = tile[tx][ty + k];
}

// C[l][r][:] = sum_q S[l][q][r] * xT[q][:]  (S union structure <= 2)
__global__ void compute_C_k() {
    int tx = threadIdx.x;                         // 0..63
    int r  = blockIdx.x * 4 + threadIdx.y;        // 0..767
    int l  = blockIdx.y;                          // 0..19
    const float4* xT4 = reinterpret_cast<const float4*>(g_xT);
    int   q0 = g_s_sidx[r * CAP + 0], q1 = g_s_sidx[r * CAP + 1];
    float w0 = g_s_val[(size_t)(l * NN + r) * CAP + 0];
    float w1 = g_s_val[(size_t)(l * NN + r) * CAP + 1];
    float4 v0 = xT4[q0 * B4 + tx];
    float4 v1 = xT4[q1 * B4 + tx];
    float4 acc;
    acc.x = w0 * v0.x + w1 * v1.x;
    acc.y = w0 * v0.y + w1 * v1.y;
    acc.z = w0 * v0.z + w1 * v1.z;
    acc.w = w0 * v0.w + w1 * v1.w;
    reinterpret_cast<float4*>(g_C)[(l * NN + r) * B4 + tx] = acc;
}

// ---------------------------------------------------------------------------
// Software grid barrier (NOT cooperative launch). All NBLK blocks are
// co-resident by construction (__launch_bounds__(256,4): 4*152=608 >= 384).
// __threadfence() on sm_103a emits CCTL.IVALL -> post-barrier loads see
// fresh data (no stale L1 hits).
// ---------------------------------------------------------------------------
__device__ __forceinline__ void grid_bar(unsigned e) {
    __syncthreads();
    __threadfence();
    if (threadIdx.x == 0) {
        unsigned t = atomicAdd(&g_bar_arrive, 1u);
        if (t == NBLK - 1u) {
            g_bar_arrive = 0u;
            __threadfence();
            atomicExch(&g_bar_epoch, e);            // release
        } else {
            while (*(volatile unsigned*)&g_bar_epoch != e) { __nanosleep(32); }
        }
    }
    __syncthreads();
    __threadfence();
}

// ---------------------------------------------------------------------------
// Persistent chain: sentinel init + first_cn + 19x(VN,CN) + output.
// Plain 8-factor products with sentinel pads (no zero-skip: reference tanh
// outputs are never exactly 0 on generic inputs, so plain product == ref).
// ---------------------------------------------------------------------------
__global__ void __launch_bounds__(256, 4) bp_chain_k(float* __restrict__ out) {
    int tx = threadIdx.x & 63;        // batch quad 0..63
    int ty = threadIdx.x >> 6;        // sub-row 0..3
    const float4* xT4 = reinterpret_cast<const float4*>(g_xT);
    const float4* C4  = reinterpret_cast<const float4*>(g_C);
    float4* g4 = reinterpret_cast<float4*>(g_g);
    float4* h4 = reinterpret_cast<float4*>(g_h);

    unsigned ep = *(volatile unsigned*)&g_bar_epoch;  // stable pre-barrier read

    // sentinel rows: xT[NN][:]=40 (tanh_half->1.0), h[HH][:]=1.0
    if (blockIdx.x == 0) {
        g_xT[NN * BB + threadIdx.x] = 40.0f;
        g_h[HH * BB + threadIdx.x]  = 1.0f;
    }
    grid_bar(++ep);

    // ---- phase 0: g = 2*atanh(clip(prod tanh(0.5*x[mask]))) ----
    for (int rb = blockIdx.x; rb < HH / 4; rb += NBLK) {
        int i = rb * 4 + ty;
        const int4* ip = reinterpret_cast<const int4*>(&g_mf_idx[i * CAP]);
        int4 i0 = ip[0], i1 = ip[1];
        int id[8] = {i0.x, i0.y, i0.z, i0.w, i1.x, i1.y, i1.z, i1.w};
        float4 v[8];
#pragma unroll
        for (int t = 0; t < 8; ++t) v[t] = xT4[id[t] * B4 + tx];
        float4 p = make_float4(1.f, 1.f, 1.f, 1.f);
#pragma unroll
        for (int t = 0; t < 8; ++t) {
            p.x *= fast_tanh_half(v[t].x);
            p.y *= fast_tanh_half(v[t].y);
            p.z *= fast_tanh_half(v[t].z);
            p.w *= fast_tanh_half(v[t].w);
        }
        float4 gg;
        gg.x = clip_atanh2(p.x); gg.y = clip_atanh2(p.y);
        gg.z = clip_atanh2(p.z); gg.w = clip_atanh2(p.w);
        g4[i * B4 + tx] = gg;
    }
    grid_bar(++ep);

    // ---- 19 iterations of (VN, CN) ----
    for (int l = 0; l < NL; ++l) {
        for (int rb = blockIdx.x; rb < HH / 4; rb += NBLK) {
            int i = rb * 4 + ty;
            int4   ii = *reinterpret_cast<const int4*>(&g_vn_sidx[i * CAP]);
            float4 ww = *reinterpret_cast<const float4*>(
                            &g_wvn_val[(size_t)(l * HH + i) * CAP]);
            int   bidx = g_bm_idx[i * CAP];
            float bw   = g_bm_val[i * CAP];
            float4 v0 = g4[ii.x * B4 + tx];
            float4 v1 = g4[ii.y * B4 + tx];
            float4 v2 = g4[ii.z * B4 + tx];
            float4 v3 = g4[ii.w * B4 + tx];
            float4 vb = C4[(l * NN + bidx) * B4 + tx];
            float4 acc;
            acc.x = ww.x*v0.x + ww.y*v1.x + ww.z*v2.x + ww.w*v3.x + bw*vb.x;
            acc.y = ww.x*v0.y + ww.y*v1.y + ww.z*v2.y + ww.w*v3.y + bw*vb.y;
            acc.z = ww.x*v0.z + ww.y*v1.z + ww.z*v2.z + ww.w*v3.z + bw*vb.z;
            acc.w = ww.x*v0.w + ww.y*v1.w + ww.z*v2.w + ww.w*v3.w + bw*vb.w;
            float4 hh;
            hh.x = fast_tanh_half(acc.x); hh.y = fast_tanh_half(acc.y);
            hh.z = fast_tanh_half(acc.z); hh.w = fast_tanh_half(acc.w);
            h4[i * B4 + tx] = hh;
        }
        grid_bar(++ep);
        for (int rb = blockIdx.x; rb < HH / 4; rb += NBLK) {
            int i = rb * 4 + ty;
            const int4* ip = reinterpret_cast<const int4*>(&g_mcn_idx[i * CAP]);
            int4 i0 = ip[0], i1 = ip[1];
            int id[8] = {i0.x, i0.y, i0.z, i0.w, i1.x, i1.y, i1.z, i1.w};
            float4 v[8];
#pragma unroll
            for (int t = 0; t < 8; ++t) v[t] = h4[id[t] * B4 + tx];
            float4 p = make_float4(1.f, 1.f, 1.f, 1.f);
#pragma unroll
            for (int t = 0; t < 8; ++t) {
                p.x *= v[t].x; p.y *= v[t].y; p.z *= v[t].z; p.w *= v[t].w;
            }
            float4 gg;
            gg.x = clip_atanh2(p.x); gg.y = clip_atanh2(p.y);
            gg.z = clip_atanh2(p.z); gg.w = clip_atanh2(p.w);
            g4[i * B4 + tx] = gg;
        }
        grid_bar(++ep);
    }

    // ---- output: sigmoid(W_out @ g + cm-gathered C_19) ----
    for (int rb = blockIdx.x; rb < NN / 4; rb += NBLK) {
        int n = rb * 4 + ty;
        int4   ii = *reinterpret_cast<const int4*>(&g_wout_idx[n * CAP]);
        float4 ww = *reinterpret_cast<const float4*>(&g_wout_val[n * CAP]);
        int   cidx = g_cm_idx[n * CAP];
        float cw   = g_cm_val[n * CAP];
        float4 v0 = g4[ii.x * B4 + tx];
        float4 v1 = g4[ii.y * B4 + tx];
        float4 v2 = g4[ii.z * B4 + tx];
        float4 v3 = g4[ii.w * B4 + tx];
        float4 vc = C4[(19 * NN + cidx) * B4 + tx];
        float4 acc;
        acc.x = ww.x*v0.x + ww.y*v1.x + ww.z*v2.x + ww.w*v3.x + cw*vc.x;
        acc.y = ww.x*v0.y + ww.y*v1.y + ww.z*v2.y + ww.w*v3.y + cw*vc.y;
        acc.z = ww.x*v0.z + ww.y*v1.z + ww.z*v2.z + ww.w*v3.z + cw*vc.z;
        acc.w = ww.x*v0.w + ww.y*v1.w + ww.z*v2.w + ww.w*v3.w + cw*vc.w;
        int b = tx * 4;
        out[(size_t)(b + 0) * NN + n] = __fdividef(1.f, 1.f + __expf(-acc.x));
        out[(size_t)(b + 1) * NN + n] = __fdividef(1.f, 1.f + __expf(-acc.y));
        out[(size_t)(b + 2) * NN + n] = __fdividef(1.f, 1.f + __expf(-acc.z));
        out[(size_t)(b + 3) * NN + n] = __fdividef(1.f, 1.f + __expf(-acc.w));
    }
}

// ---------------------------------------------------------------------------
// Host launcher (graph-capturable: kernel launches only, plain launches)
// ---------------------------------------------------------------------------
extern "C" void kernel_launch(void* const* d_in, const int* in_sizes, int n_in,
                              void* d_out, int out_size) {
    const float* x    = (const float*)d_in[0];  // [256,768]
    const float* Wvn  = (const float*)d_in[1];  // [19,3072,3072]
    const float* Wout = (const float*)d_in[2];  // [768,3072]
    const float* S    = (const float*)d_in[3];  // [20,768,768]
    const float* bm   = (const float*)d_in[4];  // [768,3072]
    const float* cm   = (const float*)d_in[5];  // [768,768]
    const float* Mf   = (const float*)d_in[6];  // [3072,768]
    const float* Mcn  = (const float*)d_in[7];  // [3072,3072]
    float* out = (float*)d_out;

    void *p_vn_si, *p_vn_sc, *p_wvn_v;
    void *p_s_si, *p_s_sc, *p_s_v;
    void *p_tmp_i, *p_tmp_v, *p_tmp_c;
    void *p_mcn_i, *p_mcn_c, *p_mf_i, *p_mf_c;
    void *p_wo_i, *p_wo_v, *p_wo_c;
    void *p_bm_i, *p_bm_v, *p_bm_c;
    void *p_cm_i, *p_cm_v, *p_cm_c;
    cudaGetSymbolAddress(&p_vn_si, g_vn_sidx);
    cudaGetSymbolAddress(&p_vn_sc, g_vn_scnt);
    cudaGetSymbolAddress(&p_wvn_v, g_wvn_val);
    cudaGetSymbolAddress(&p_s_si,  g_s_sidx);
    cudaGetSymbolAddress(&p_s_sc,  g_s_scnt);
    cudaGetSymbolAddress(&p_s_v,   g_s_val);
    cudaGetSymbolAddress(&p_tmp_i, g_tmp_idx);
    cudaGetSymbolAddress(&p_tmp_v, g_tmp_val);
    cudaGetSymbolAddress(&p_tmp_c, g_tmp_cnt);
    cudaGetSymbolAddress(&p_mcn_i, g_mcn_idx);
    cudaGetSymbolAddress(&p_mcn_c, g_mcn_cnt);
    cudaGetSymbolAddress(&p_mf_i,  g_mf_idx);
    cudaGetSymbolAddress(&p_mf_c,  g_mf_cnt);
    cudaGetSymbolAddress(&p_wo_i,  g_wout_idx);
    cudaGetSymbolAddress(&p_wo_v,  g_wout_val);
    cudaGetSymbolAddress(&p_wo_c,  g_wout_cnt);
    cudaGetSymbolAddress(&p_bm_i,  g_bm_idx);
    cudaGetSymbolAddress(&p_bm_v,  g_bm_val);
    cudaGetSymbolAddress(&p_bm_c,  g_bm_cnt);
    cudaGetSymbolAddress(&p_cm_i,  g_cm_idx);
    cudaGetSymbolAddress(&p_cm_v,  g_cm_val);
    cudaGetSymbolAddress(&p_cm_c,  g_cm_cnt);

    // --- W_vn: structure from layers 0+1 (union), then gather all 19 layers ---
    extract_rows_fast<HH><<<(2 * HH * 32 + 255) / 256, 256>>>(Wvn, 2 * HH,
        (int*)p_tmp_i, (float*)nullptr, (int*)p_tmp_c, 0);
    union_rows_k<<<(HH + 255) / 256, 256>>>((const int*)p_tmp_i,
        (const int*)p_tmp_c, HH, (int*)p_vn_si, (int*)p_vn_sc);
    gather_vals_k<<<(NL * HH * CAP + 255) / 256, 256>>>(Wvn,
        (size_t)HH * HH, (size_t)HH, (size_t)1, HH, NL,
        (const int*)p_vn_si, (const int*)p_vn_sc, (float*)p_wvn_v);

    // --- mask matrices: pad idx -> sentinel rows ---
    extract_rows_fast<HH><<<(HH * 32 + 255) / 256, 256>>>(Mcn, HH,
        (int*)p_mcn_i, (float*)nullptr, (int*)p_mcn_c, HH);
    extract_rows_fast<NN><<<(HH * 32 + 255) / 256, 256>>>(Mf, HH,
        (int*)p_mf_i, (float*)nullptr, (int*)p_mf_c, NN);
    extract_rows_fast<HH><<<(NN * 32 + 255) / 256, 256>>>(Wout, NN,
        (int*)p_wo_i, (float*)p_wo_v, (int*)p_wo_c, 0);

    // --- column-sparse matrices ---
    extract_cols_k<<<dim3((HH + 255) / 256, 1), 256>>>(bm, NN, HH, 0,
        (int*)p_bm_i, (float*)p_bm_v, (int*)p_bm_c);
    extract_cols_k<<<dim3((NN + 255) / 256, 1), 256>>>(cm, NN, NN, 0,
        (int*)p_cm_i, (float*)p_cm_v, (int*)p_cm_c);

    // --- S: structure from layers 0+1 (union), then gather all 20 layers ---
    extract_cols_k<<<dim3((NN + 255) / 256, 2), 256>>>(S, NN, NN,
        (size_t)NN * NN, (int*)p_tmp_i, (float*)p_tmp_v, (int*)p_tmp_c);
    union_rows_k<<<(NN + 255) / 256, 256>>>((const int*)p_tmp_i,
        (const int*)p_tmp_c, NN, (int*)p_s_si, (int*)p_s_sc);
    gather_vals_k<<<(20 * NN * CAP + 255) / 256, 256>>>(S,
        (size_t)NN * NN, (size_t)1, (size_t)NN, NN, 20,
        (const int*)p_s_si, (const int*)p_s_sc, (float*)p_s_v);

    // --- pre-chain compute ---
    transpose_x_k<<<dim3(NN / 32, BB / 32), dim3(32, 8)>>>(x);
    compute_C_k<<<dim3(NN / 4, 20), dim3(64, 4)>>>();

    // --- persistent chain (plain launch + software grid barrier) ---
    bp_chain_k<<<NBLK, 256>>>(out);
}